// round 6
// baseline (speedup 1.0000x reference)
#include <cuda_runtime.h>
#include <cstdint>

using ull  = unsigned long long;
using uint = unsigned int;

static constexpr int NN    = 16384;  // points per batch
static constexpr int KK    = 16;     // neighbors
static constexpr int CC    = 64;     // feature channels
static constexpr int DD    = 64;     // mlp out channels
static constexpr int WARPS = 8;      // warps per block
static constexpr int BLOCKS = 148 * 4; // one wave at occupancy 4
static constexpr float SLOPE = 0.1f;

#define FULLM 0xFFFFFFFFu
static constexpr ull ABSM = 0x7FFFFFFF7FFFFFFFULL;

// ---- packed f32x2 helpers ----
__device__ __forceinline__ ull pfma(ull a, ull b, ull c) {
    ull d; asm("fma.rn.f32x2 %0, %1, %2, %3;" : "=l"(d) : "l"(a), "l"(b), "l"(c)); return d;
}
__device__ __forceinline__ ull padd(ull a, ull b) {
    ull d; asm("add.rn.f32x2 %0, %1, %2;" : "=l"(d) : "l"(a), "l"(b)); return d;
}
__device__ __forceinline__ ull pmul(ull a, ull b) {
    ull d; asm("mul.rn.f32x2 %0, %1, %2;" : "=l"(d) : "l"(a), "l"(b)); return d;
}
__device__ __forceinline__ ull dup2(float x) {
    unsigned u = __float_as_uint(x);
    ull r; asm("mov.b64 %0, {%1, %1};" : "=l"(r) : "r"(u)); return r;
}
__device__ __forceinline__ ull pk2(float lo, float hi) {
    ull r; asm("mov.b64 %0, {%1, %2};" : "=l"(r)
               : "r"(__float_as_uint(lo)), "r"(__float_as_uint(hi))); return r;
}
__device__ __forceinline__ ull shflx64(ull x, int m) {
    uint lo = (uint)x, hi = (uint)(x >> 32);
    lo = __shfl_xor_sync(FULLM, lo, m);
    hi = __shfl_xor_sync(FULLM, hi, m);
    return (ull)lo | ((ull)hi << 32);
}

__global__ __launch_bounds__(WARPS * 32, 4)
void lfa_kernel(const float* __restrict__ features,
                const float* __restrict__ geom,
                const float* __restrict__ w,
                const float* __restrict__ bias,
                const long long* __restrict__ nidx,
                float* __restrict__ out,
                int npts)
{
    const int lane = threadIdx.x & 31;
    const int wid  = threadIdx.x >> 5;
    const int p    = lane & 15;        // sub-lane within half
    const int half = lane >> 4;        // k-half: 0 -> k 0-7, 1 -> k 8-15

    // ---- per-warp index dtype detection ----
    // Probe first 16 values as int64: if data is really int32, an 8B read packs
    // two indices -> value out of [0,NN) w.h.p.
    long long probe = nidx[p];
    bool okp = (probe >= 0) && (probe < (long long)NN);
    unsigned bal = __ballot_sync(FULLM, okp);
    const bool is64 = ((bal & 0xFFFFu) == 0xFFFFu);

    // ---- weights: lane owns d-pairs A=(2p, 2p+1), B=(2p+32, 2p+33) ----
    const float4* w4 = reinterpret_cast<const float4*>(w);
    float4 wa = w4[2 * p],      wb = w4[2 * p + 1];
    float4 wc = w4[2 * p + 32], wd = w4[2 * p + 33];
    const ull wA0 = pk2(wa.x, wb.x), wA1 = pk2(wa.y, wb.y);
    const ull wA2 = pk2(wa.z, wb.z), wA3 = pk2(wa.w, wb.w);
    const ull wB0 = pk2(wc.x, wd.x), wB1 = pk2(wc.y, wd.y);
    const ull wB2 = pk2(wc.z, wd.z), wB3 = pk2(wc.w, wd.w);
    const ull bA  = *reinterpret_cast<const ull*>(bias + 2 * p);
    const ull bB  = *reinterpret_cast<const ull*>(bias + 2 * p + 32);

    const ull C1 = dup2((1.0f + SLOPE) * 0.5f / (float)KK);
    const ull C2 = dup2((1.0f - SLOPE) * 0.5f / (float)KK);
    const ull CM = dup2(1.0f / (float)KK);

    const int gwarp  = blockIdx.x * WARPS + wid;
    const int stride = BLOCKS * WARPS;

    // ---- prefetch first point's idx (lanes 0-15, one LDG) ----
    int icur = 0;
    if (gwarp < npts && lane < KK) {
        if (is64) icur = (int)nidx[(size_t)gwarp * KK + lane];
        else      icur = reinterpret_cast<const int*>(nidx)[(size_t)gwarp * KK + lane];
    }

    for (int pt = gwarp; pt < npts; pt += stride) {
        const int bb = pt >> 14;   // pt / NN

        // ---- broadcast this point's 8 indices for my half (regs already resident) ----
        const int r0 = __shfl_sync(FULLM, icur, 0 + 8 * half);
        const int r1 = __shfl_sync(FULLM, icur, 1 + 8 * half);
        const int r2 = __shfl_sync(FULLM, icur, 2 + 8 * half);
        const int r3 = __shfl_sync(FULLM, icur, 3 + 8 * half);
        const int r4 = __shfl_sync(FULLM, icur, 4 + 8 * half);
        const int r5 = __shfl_sync(FULLM, icur, 5 + 8 * half);
        const int r6 = __shfl_sync(FULLM, icur, 6 + 8 * half);
        const int r7 = __shfl_sync(FULLM, icur, 7 + 8 * half);

        // ---- gather: 8 x LDG.128 (lane owns channels 4p..4p+3 of its k-half) ----
        const float* fb = features + (size_t)bb * NN * CC + 4 * p;
        ulonglong2 v0 = *reinterpret_cast<const ulonglong2*>(fb + (size_t)r0 * CC);
        ulonglong2 v1 = *reinterpret_cast<const ulonglong2*>(fb + (size_t)r1 * CC);
        ulonglong2 v2 = *reinterpret_cast<const ulonglong2*>(fb + (size_t)r2 * CC);
        ulonglong2 v3 = *reinterpret_cast<const ulonglong2*>(fb + (size_t)r3 * CC);
        ulonglong2 v4 = *reinterpret_cast<const ulonglong2*>(fb + (size_t)r4 * CC);
        ulonglong2 v5 = *reinterpret_cast<const ulonglong2*>(fb + (size_t)r5 * CC);
        ulonglong2 v6 = *reinterpret_cast<const ulonglong2*>(fb + (size_t)r6 * CC);
        ulonglong2 v7 = *reinterpret_cast<const ulonglong2*>(fb + (size_t)r7 * CC);

        // ---- prefetch next point's idx while gathers/compute are in flight ----
        const int ptn = pt + stride;
        if (ptn < npts && lane < KK) {
            if (is64) icur = (int)nidx[(size_t)ptn * KK + lane];
            else      icur = reinterpret_cast<const int*>(nidx)[(size_t)ptn * KK + lane];
        }

        // ---- geom MLP: uniform LDG.128 per k (no smem, no sync) ----
        // half-split over k: this lane covers k = 8*half .. 8*half+7
        const float4* gp = reinterpret_cast<const float4*>(geom) + (size_t)pt * KK + 8 * half;
        ull sA = 0ULL, aA = 0ULL, sB = 0ULL, aB = 0ULL;
#pragma unroll
        for (int i = 0; i < 8; i++) {
            float4 gk = gp[i];                     // warp-uniform LDG.128, L1 streamed
            ull g0 = dup2(gk.x), g1 = dup2(gk.y), g2 = dup2(gk.z), g3 = dup2(gk.w);
            ull xA = pfma(g3, wA3, pfma(g2, wA2, pfma(g1, wA1, pfma(g0, wA0, bA))));
            ull xB = pfma(g3, wB3, pfma(g2, wB2, pfma(g1, wB1, pfma(g0, wB0, bB))));
            sA = padd(sA, xA);  aA = padd(aA, xA & ABSM);
            sB = padd(sB, xB);  aB = padd(aB, xB & ABSM);
        }
        // prescale, THEN combine k-halves (only t crosses lanes: 2 shflx64 = 4 SHFL)
        // mean_k lrelu(x) = c1*sum(x) + c2*sum(|x|)   (slope 0.1)
        ull tA = pfma(sA, C1, pmul(aA, C2));
        ull tB = pfma(sB, C1, pmul(aB, C2));
        tA = padd(tA, shflx64(tA, 16));
        tB = padd(tB, shflx64(tB, 16));

        // ---- gather mean: tree-sum 8 rows, prescale, k-half butterfly ----
        ull ac0 = padd(padd(v0.x, v1.x), padd(v2.x, v3.x));
        ull ac1 = padd(padd(v0.y, v1.y), padd(v2.y, v3.y));
        ac0 = padd(ac0, padd(padd(v4.x, v5.x), padd(v6.x, v7.x)));
        ac1 = padd(ac1, padd(padd(v4.y, v5.y), padd(v6.y, v7.y)));
        ac0 = pmul(ac0, CM);
        ac1 = pmul(ac1, CM);
        ac0 = padd(ac0, shflx64(ac0, 16));
        ac1 = padd(ac1, shflx64(ac1, 16));

        // ---- stores: every lane 2 x STG.64, each group contiguous 256B ----
        float* op = out + (size_t)pt * (DD + CC);
        // t: half 0 stores pair (2p,2p+1), half 1 stores (2p+32,2p+33)
        *reinterpret_cast<ull*>(op + 2 * p + 32 * half) = half ? tB : tA;
        // gather: half 0 stores channels (4p,4p+1), half 1 stores (4p+2,4p+3)
        *reinterpret_cast<ull*>(op + DD + 4 * p + 2 * half) = half ? ac1 : ac0;
    }
}

extern "C" void kernel_launch(void* const* d_in, const int* in_sizes, int n_in,
                              void* d_out, int out_size)
{
    const float*     features = (const float*)d_in[0];
    const float*     geom     = (const float*)d_in[1];
    const float*     w        = (const float*)d_in[2];
    const float*     b        = (const float*)d_in[3];
    const long long* nidx     = (const long long*)d_in[4];

    const int npts = in_sizes[1] / (KK * 4);             // B*N from geom

    lfa_kernel<<<BLOCKS, WARPS * 32>>>(features, geom, w, b, nidx, (float*)d_out, npts);
}

// round 8
// speedup vs baseline: 1.3806x; 1.3806x over previous
#include <cuda_runtime.h>
#include <cstdint>

using ull  = unsigned long long;
using uint = unsigned int;

static constexpr int NN    = 16384;  // points per batch
static constexpr int KK    = 16;     // neighbors
static constexpr int CC    = 64;     // feature channels
static constexpr int DD    = 64;     // mlp out channels
static constexpr int WARPS = 8;      // warps per block
static constexpr int PPW   = 8;      // points per warp (grid sizing, as R2)
static constexpr float SLOPE = 0.1f;

#define FULLM 0xFFFFFFFFu
static constexpr ull ABSM = 0x7FFFFFFF7FFFFFFFULL;

// ---- packed f32x2 helpers (Blackwell FFMA2 path) ----
__device__ __forceinline__ ull pfma(ull a, ull b, ull c) {
    ull d; asm("fma.rn.f32x2 %0, %1, %2, %3;" : "=l"(d) : "l"(a), "l"(b), "l"(c)); return d;
}
__device__ __forceinline__ ull padd(ull a, ull b) {
    ull d; asm("add.rn.f32x2 %0, %1, %2;" : "=l"(d) : "l"(a), "l"(b)); return d;
}
__device__ __forceinline__ ull pmul(ull a, ull b) {
    ull d; asm("mul.rn.f32x2 %0, %1, %2;" : "=l"(d) : "l"(a), "l"(b)); return d;
}
__device__ __forceinline__ ull dup2(float x) {
    unsigned u = __float_as_uint(x);
    ull r; asm("mov.b64 %0, {%1, %1};" : "=l"(r) : "r"(u)); return r;
}
__device__ __forceinline__ ull pk2(float lo, float hi) {
    ull r; asm("mov.b64 %0, {%1, %2};" : "=l"(r)
               : "r"(__float_as_uint(lo)), "r"(__float_as_uint(hi))); return r;
}
__device__ __forceinline__ ull shflx64(ull x, int m) {
    uint lo = (uint)x, hi = (uint)(x >> 32);
    lo = __shfl_xor_sync(FULLM, lo, m);
    hi = __shfl_xor_sync(FULLM, hi, m);
    return (ull)lo | ((ull)hi << 32);
}

__global__ __launch_bounds__(WARPS * 32)
void lfa_kernel(const float* __restrict__ features,
                const float* __restrict__ geom,
                const float* __restrict__ w,
                const float* __restrict__ bias,
                const long long* __restrict__ nidx,
                float* __restrict__ out,
                int npts)
{
    // geom per warp, each scalar pre-duplicated to f32x2 at staging time
    __shared__ alignas(16) ull sg[WARPS][KK][4];

    const int lane = threadIdx.x & 31;
    const int wid  = threadIdx.x >> 5;
    const int p    = lane & 15;        // sub-lane within half
    const int half = lane >> 4;        // k-half: 0 -> k 0-7, 1 -> k 8-15

    // ---- per-warp index dtype detection ----
    // Probe first 16 values as int64: if data is really int32, an 8B read packs
    // two indices -> value out of [0,NN) w.h.p.
    long long probe = nidx[p];
    bool okp = (probe >= 0) && (probe < (long long)NN);
    unsigned bal = __ballot_sync(FULLM, okp);
    const bool is64 = ((bal & 0xFFFFu) == 0xFFFFu);

    // ---- weights: lane owns d-pairs A=(2p, 2p+1), B=(2p+32, 2p+33) ----
    const float4* w4 = reinterpret_cast<const float4*>(w);
    float4 wa = w4[2 * p],      wb = w4[2 * p + 1];
    float4 wc = w4[2 * p + 32], wd = w4[2 * p + 33];
    const ull wA0 = pk2(wa.x, wb.x), wA1 = pk2(wa.y, wb.y);
    const ull wA2 = pk2(wa.z, wb.z), wA3 = pk2(wa.w, wb.w);
    const ull wB0 = pk2(wc.x, wd.x), wB1 = pk2(wc.y, wd.y);
    const ull wB2 = pk2(wc.z, wd.z), wB3 = pk2(wc.w, wd.w);
    const ull bA  = *reinterpret_cast<const ull*>(bias + 2 * p);
    const ull bB  = *reinterpret_cast<const ull*>(bias + 2 * p + 32);

    const ull C1 = dup2((1.0f + SLOPE) * 0.5f / (float)KK);
    const ull C2 = dup2((1.0f - SLOPE) * 0.5f / (float)KK);
    const ull CM = dup2(1.0f / (float)KK);

    const int gwarp  = blockIdx.x * WARPS + wid;
    const int stride = gridDim.x * WARPS;

    // ---- prefetch first point's idx (lanes 0-15) ----
    int icur = 0;
    if (gwarp < npts && lane < KK) {
        if (is64) icur = (int)nidx[(size_t)gwarp * KK + lane];
        else      icur = reinterpret_cast<const int*>(nidx)[(size_t)gwarp * KK + lane];
    }

    for (int pt = gwarp; pt < npts; pt += stride) {
        const int bb = pt >> 14;   // pt / NN

        // ---- stage geom pre-duplicated (lanes 0-15); capture idx ----
        const int idxv = icur;
        if (lane < KK) {
            float4 g = reinterpret_cast<const float4*>(geom)[(size_t)pt * KK + lane];
            ulonglong2 d0, d1;
            d0.x = dup2(g.x); d0.y = dup2(g.y);
            d1.x = dup2(g.z); d1.y = dup2(g.w);
            ulonglong2* dst = reinterpret_cast<ulonglong2*>(&sg[wid][lane][0]);
            dst[0] = d0;
            dst[1] = d1;
        }
        __syncwarp();

        // ---- broadcast my k-half's 8 indices ----
        const int r0 = __shfl_sync(FULLM, idxv, 0 + 8 * half);
        const int r1 = __shfl_sync(FULLM, idxv, 1 + 8 * half);
        const int r2 = __shfl_sync(FULLM, idxv, 2 + 8 * half);
        const int r3 = __shfl_sync(FULLM, idxv, 3 + 8 * half);
        const int r4 = __shfl_sync(FULLM, idxv, 4 + 8 * half);
        const int r5 = __shfl_sync(FULLM, idxv, 5 + 8 * half);
        const int r6 = __shfl_sync(FULLM, idxv, 6 + 8 * half);
        const int r7 = __shfl_sync(FULLM, idxv, 7 + 8 * half);

        // ---- gather: 8 x LDG.128 (lane owns channels 4p..4p+3 of its k-half) ----
        const float* fb = features + (size_t)bb * NN * CC + 4 * p;
        ulonglong2 v0 = *reinterpret_cast<const ulonglong2*>(fb + (size_t)r0 * CC);
        ulonglong2 v1 = *reinterpret_cast<const ulonglong2*>(fb + (size_t)r1 * CC);
        ulonglong2 v2 = *reinterpret_cast<const ulonglong2*>(fb + (size_t)r2 * CC);
        ulonglong2 v3 = *reinterpret_cast<const ulonglong2*>(fb + (size_t)r3 * CC);
        ulonglong2 v4 = *reinterpret_cast<const ulonglong2*>(fb + (size_t)r4 * CC);
        ulonglong2 v5 = *reinterpret_cast<const ulonglong2*>(fb + (size_t)r5 * CC);
        ulonglong2 v6 = *reinterpret_cast<const ulonglong2*>(fb + (size_t)r6 * CC);
        ulonglong2 v7 = *reinterpret_cast<const ulonglong2*>(fb + (size_t)r7 * CC);

        // ---- prefetch next point's idx while gathers are in flight ----
        const int ptn = pt + stride;
        if (ptn < npts && lane < KK) {
            if (is64) icur = (int)nidx[(size_t)ptn * KK + lane];
            else      icur = reinterpret_cast<const int*>(nidx)[(size_t)ptn * KK + lane];
        }

        // ---- geom MLP: 8 iters, 2 broadcast LDS.128 each, no dup-MOVs ----
        ull sA = 0ULL, aA = 0ULL, sB = 0ULL, aB = 0ULL;
#pragma unroll
        for (int i = 0; i < 8; i++) {
            const ulonglong2* gk =
                reinterpret_cast<const ulonglong2*>(&sg[wid][i + 8 * half][0]);
            ulonglong2 ga = gk[0];     // (dup g0, dup g1)
            ulonglong2 gb = gk[1];     // (dup g2, dup g3)
            ull xA = pfma(gb.y, wA3, pfma(gb.x, wA2, pfma(ga.y, wA1, pfma(ga.x, wA0, bA))));
            ull xB = pfma(gb.y, wB3, pfma(gb.x, wB2, pfma(ga.y, wB1, pfma(ga.x, wB0, bB))));
            sA = padd(sA, xA);  aA = padd(aA, xA & ABSM);
            sB = padd(sB, xB);  aB = padd(aB, xB & ABSM);
        }
        // prescale, THEN combine k-halves (butterfly only t: 4 SHFL total)
        // mean_k lrelu(x) = c1*sum(x) + c2*sum(|x|)   (slope 0.1)
        ull tA = pfma(sA, C1, pmul(aA, C2));
        ull tB = pfma(sB, C1, pmul(aB, C2));
        tA = padd(tA, shflx64(tA, 16));
        tB = padd(tB, shflx64(tB, 16));

        // ---- gather mean: tree-sum 8 rows, prescale, k-half butterfly ----
        ull ac0 = padd(padd(v0.x, v1.x), padd(v2.x, v3.x));
        ull ac1 = padd(padd(v0.y, v1.y), padd(v2.y, v3.y));
        ac0 = padd(ac0, padd(padd(v4.x, v5.x), padd(v6.x, v7.x)));
        ac1 = padd(ac1, padd(padd(v4.y, v5.y), padd(v6.y, v7.y)));
        ac0 = pmul(ac0, CM);
        ac1 = pmul(ac1, CM);
        ac0 = padd(ac0, shflx64(ac0, 16));
        ac1 = padd(ac1, shflx64(ac1, 16));

        // ---- stores: every lane 2 x STG.64, each group contiguous 256B ----
        float* op = out + (size_t)pt * (DD + CC);
        // t: half 0 stores pair (2p,2p+1), half 1 stores (2p+32,2p+33)
        *reinterpret_cast<ull*>(op + 2 * p + 32 * half) = half ? tB : tA;
        // gather: half 0 stores channels (4p,4p+1), half 1 stores (4p+2,4p+3)
        *reinterpret_cast<ull*>(op + DD + 4 * p + 2 * half) = half ? ac1 : ac0;
    }
}

extern "C" void kernel_launch(void* const* d_in, const int* in_sizes, int n_in,
                              void* d_out, int out_size)
{
    const float*     features = (const float*)d_in[0];
    const float*     geom     = (const float*)d_in[1];
    const float*     w        = (const float*)d_in[2];
    const float*     b        = (const float*)d_in[3];
    const long long* nidx     = (const long long*)d_in[4];

    const int npts = in_sizes[1] / (KK * 4);             // B*N from geom
    int blocks = (npts + WARPS * PPW - 1) / (WARPS * PPW);
    if (blocks < 1) blocks = 1;

    lfa_kernel<<<blocks, WARPS * 32>>>(features, geom, w, b, nidx, (float*)d_out, npts);
}